// round 1
// baseline (speedup 1.0000x reference)
#include <cuda_runtime.h>

// IntentGCN fused kernel for GB300 (sm_103a).
// Shapes: N=32, C=64, T=300, V=25, K=3, H=4, DK=DV=16, C_OUT=64. 9600 (n,t) slices.
// One persistent CTA per SM; weights staged in smem once per block; each slice
// computed entirely in shared memory (no global intermediates).

#define NTH 256
#define GRID 152
#define NSLICE 9600
#define CC 64
#define VV 25
#define TT 300

__device__ int g_counter;

__global__ void reset_counter_kernel() { g_counter = 0; }

// ---- shared memory layout (float offsets) ----
// Combined weight matrix sW[c][j], j in [0,384), row stride 385 (conflict-free cols):
//   j in [0,192):  conv (operand fa)      sW[c][o]      = conv_w[o*64+c]
//   j in [192,256): k   (operand fa)      sW[c][192+d]  = wk[c*64+d]
//   j in [256,320): v   (operand fa)      sW[c][256+d]  = wv[c*64+d]
//   j in [320,384): q   (operand qn)      sW[c][320+d]  = wq[c*64+d]
constexpr int SW_S   = 385;
constexpr int OFF_SW  = 0;                    // 64*385 = 24640
constexpr int OFF_SA  = OFF_SW + 64*SW_S;     // 1875  A[k][v][w]
constexpr int OFF_SFC = OFF_SA + 1875;        // 4096  fc_w[e][c]
constexpr int OFF_SC1 = OFF_SFC + 4096;       // 64
constexpr int OFF_SH1 = OFF_SC1 + 64;         // 64
constexpr int OFF_SC2 = OFF_SH1 + 64;         // 64
constexpr int OFF_SH2 = OFF_SC2 + 64;         // 64
constexpr int OFF_LNG = OFF_SH2 + 64;         // 64
constexpr int OFF_LNB = OFF_LNG + 64;         // 64
constexpr int OFF_CB  = OFF_LNB + 64;         // 192   conv_b
constexpr int FA_S   = 65;
constexpr int OFF_FA  = OFF_CB + 192;         // 26*65 (row 25 is a dummy pad row)
constexpr int OFF_QN  = OFF_FA + 26*FA_S;     // 26*65
constexpr int GO_S   = 385;
constexpr int OFF_GO  = OFF_QN + 26*FA_S;     // 25*385 GEMM out [v][j]
constexpr int OFF_ATT = OFF_GO + 25*GO_S;     // 2500  attn[h][i][j]
constexpr int OFF_XO  = OFF_ATT + 2500;       // 25*65 attention output [v][e]
constexpr int OFF_FCA = OFF_XO + 25*FA_S;     // 1600  fixed-branch out [c][w]
constexpr int SMEM_FLOATS = OFF_FCA + 1600;   // 49917 floats = 199668 B

__global__ void __launch_bounds__(NTH, 1)
gcn_kernel(const float* __restrict__ x,      const float* __restrict__ A,
           const float* __restrict__ bn1g,   const float* __restrict__ bn1b,
           const float* __restrict__ bn1m,   const float* __restrict__ bn1v,
           const float* __restrict__ conv_w, const float* __restrict__ conv_b,
           const float* __restrict__ ln_g,   const float* __restrict__ ln_b,
           const float* __restrict__ wq,     const float* __restrict__ wk,
           const float* __restrict__ wv,     const float* __restrict__ fc_w,
           const float* __restrict__ gatep,
           const float* __restrict__ bn2g,   const float* __restrict__ bn2b,
           const float* __restrict__ bn2m,   const float* __restrict__ bn2v,
           float* __restrict__ out)
{
    extern __shared__ float sm[];
    float* sW  = sm + OFF_SW;
    float* sA  = sm + OFF_SA;
    float* sfc = sm + OFF_SFC;
    float* sc1 = sm + OFF_SC1; float* sh1 = sm + OFF_SH1;
    float* sc2 = sm + OFF_SC2; float* sh2 = sm + OFF_SH2;
    float* lng = sm + OFF_LNG; float* lnb = sm + OFF_LNB;
    float* scb = sm + OFF_CB;
    float* fa  = sm + OFF_FA;
    float* qn  = sm + OFF_QN;
    float* go  = sm + OFF_GO;
    float* att = sm + OFF_ATT;
    float* xo  = sm + OFF_XO;
    float* fcA = sm + OFF_FCA;

    const int tid = threadIdx.x;
    const float gate = __ldg(gatep);

    // ---- one-time weight staging ----
    // conv: coalesced read, conflict-free padded write
    for (int i = tid; i < 192*64; i += NTH) {
        int o = i >> 6, c = i & 63;
        sW[c*SW_S + o] = conv_w[i];
    }
    for (int i = tid; i < 4096; i += NTH) {
        int c = i >> 6, d = i & 63;
        sW[c*SW_S + 192 + d] = wk[i];
        sW[c*SW_S + 256 + d] = wv[i];
        sW[c*SW_S + 320 + d] = wq[i];
        sfc[i] = fc_w[i];
    }
    for (int i = tid; i < 1875; i += NTH) sA[i] = A[i];
    if (tid < 192) scb[tid] = conv_b[tid];
    if (tid < 64) {
        float s1 = bn1g[tid] * rsqrtf(bn1v[tid] + 1e-5f);
        sc1[tid] = s1; sh1[tid] = bn1b[tid] - bn1m[tid] * s1;
        float s2 = bn2g[tid] * rsqrtf(bn2v[tid] + 1e-5f);
        sc2[tid] = s2; sh2[tid] = bn2b[tid] - bn2m[tid] * s2;
        lng[tid] = ln_g[tid]; lnb[tid] = ln_b[tid];
    }
    __shared__ int s_slice;
    __syncthreads();

    const int wid = tid >> 5, lane = tid & 31;

    for (;;) {
        if (tid == 0) s_slice = atomicAdd(&g_counter, 1);
        __syncthreads();               // also fences previous slice's readers
        const int slice = s_slice;
        if (slice >= NSLICE) break;
        const int n = slice / TT, t = slice - n * TT;

        // ---- Step A: load x slice, BN1, transpose -> fa[v][c] ----
        {
            const float* xs = x + ((long)n * CC * TT + t) * VV;
            for (int i = tid; i < CC * VV; i += NTH) {
                int c = i / VV, v = i - c * VV;
                float val = xs[(long)c * TT * VV + v];
                fa[v * FA_S + c] = fmaf(val, sc1[c], sh1[c]);
            }
        }
        __syncthreads();

        // ---- Step A2: LayerNorm per joint -> qn[v][c] ----
        for (int v = wid; v < VV; v += 8) {
            float a0 = fa[v * FA_S + lane];
            float a1 = fa[v * FA_S + 32 + lane];
            float s = a0 + a1, sq = a0 * a0 + a1 * a1;
            #pragma unroll
            for (int off = 16; off; off >>= 1) {
                s  += __shfl_xor_sync(0xffffffffu, s, off);
                sq += __shfl_xor_sync(0xffffffffu, sq, off);
            }
            float mu = s * (1.f / 64.f);
            float var = sq * (1.f / 64.f) - mu * mu;
            float rstd = rsqrtf(var + 1e-6f);
            qn[v * FA_S + lane]      = fmaf((a0 - mu) * rstd, lng[lane],      lnb[lane]);
            qn[v * FA_S + 32 + lane] = fmaf((a1 - mu) * rstd, lng[lane + 32], lnb[lane + 32]);
        }
        __syncthreads();

        // ---- Step B: combined GEMM [25 x 64] @ [64 x 384] -> go[v][j] ----
        // thread = (vg, jg): vg=tid>>7 owns 13 v-rows (vg1's 13th is dummy),
        // jg in [0,128) owns columns {jg, jg+128, jg+256}.
        {
            const int vg = tid >> 7;
            const int jg = tid & 127;
            const int vbase = vg * 13;
            const float* opA2 = (jg >= 64) ? qn : fa;   // col jg+256: >=320 => q (qn)
            float acc[13][3];
            #pragma unroll
            for (int vi = 0; vi < 13; vi++) { acc[vi][0]=0.f; acc[vi][1]=0.f; acc[vi][2]=0.f; }
            const float* fap = fa   + vbase * FA_S;
            const float* f2p = opA2 + vbase * FA_S;
            for (int c = 0; c < CC; c++) {
                float w0 = sW[c * SW_S + jg];
                float w1 = sW[c * SW_S + 128 + jg];
                float w2 = sW[c * SW_S + 256 + jg];
                #pragma unroll
                for (int vi = 0; vi < 13; vi++) {
                    float f  = fap[vi * FA_S + c];
                    float f2 = f2p[vi * FA_S + c];
                    acc[vi][0] = fmaf(f,  w0, acc[vi][0]);
                    acc[vi][1] = fmaf(f,  w1, acc[vi][1]);
                    acc[vi][2] = fmaf(f2, w2, acc[vi][2]);
                }
            }
            float b0 = scb[jg];
            float b1 = (jg < 64) ? scb[128 + jg] : 0.f;
            #pragma unroll
            for (int vi = 0; vi < 13; vi++) {
                int v = vbase + vi;
                if (v < VV) {
                    go[v * GO_S + jg]       = acc[vi][0] + b0;
                    go[v * GO_S + 128 + jg] = acc[vi][1] + b1;
                    go[v * GO_S + 256 + jg] = acc[vi][2];
                }
            }
        }
        __syncthreads();

        // ---- Step C: fixed-branch A contraction  fcA[c][w] = sum_{k,v} go[v][k*64+c]*A[k][v][w]
        for (int i = tid; i < CC * VV; i += NTH) {
            int c = i / VV, w = i - c * VV;
            float acc = 0.f;
            #pragma unroll
            for (int k = 0; k < 3; k++) {
                const float* gp = go + k * 64 + c;
                const float* ap = sA + (k * VV) * VV + w;
                #pragma unroll
                for (int v = 0; v < VV; v++)
                    acc = fmaf(gp[v * GO_S], ap[v * VV], acc);
            }
            fcA[c * VV + w] = acc;
        }
        // ---- Step D1: attention scores (same phase; both read-only on go) ----
        for (int i = tid; i < 4 * VV * VV; i += NTH) {
            int h = i / 625, r = i - h * 625;
            int qi = r / VV, kj = r - qi * VV;
            const float* qp = go + qi * GO_S + 320 + h * 16;
            const float* kp = go + kj * GO_S + 192 + h * 16;
            float acc = 0.f;
            #pragma unroll
            for (int d = 0; d < 16; d++) acc = fmaf(qp[d], kp[d], acc);
            att[(h * VV + qi) * VV + kj] = acc * 0.25f;
        }
        __syncthreads();

        // ---- Step D2: softmax over last dim (100 rows of 25) ----
        if (tid < 100) {
            float* row = att + tid * VV;
            float m = row[0];
            #pragma unroll
            for (int j = 1; j < VV; j++) m = fmaxf(m, row[j]);
            float e[VV]; float s = 0.f;
            #pragma unroll
            for (int j = 0; j < VV; j++) { e[j] = __expf(row[j] - m); s += e[j]; }
            float inv = 1.f / s;
            #pragma unroll
            for (int j = 0; j < VV; j++) row[j] = e[j] * inv;
        }
        __syncthreads();

        // ---- Step D3: xo[v][e] = sum_j attn[h,v,j] * vv[j][e] ----
        for (int i = tid; i < VV * CC; i += NTH) {
            int v = i >> 6, e = i & 63, h = e >> 4;
            const float* ap = att + (h * VV + v) * VV;
            const float* vp = go + 256 + e;
            float acc = 0.f;
            #pragma unroll
            for (int j = 0; j < VV; j++) acc = fmaf(ap[j], vp[j * GO_S], acc);
            xo[v * FA_S + e] = acc;
        }
        __syncthreads();

        // ---- Step E/F: fc + residual, gate mix, BN2, ReLU, store ----
        {
            float* os = out + ((long)n * CC * TT + t) * VV;
            for (int i = tid; i < CC * VV; i += NTH) {
                int c = i / VV, v = i - c * VV;
                const float* xp = xo + v * FA_S;
                const float* fp = sfc + c;
                float acc = 0.f;
                #pragma unroll
                for (int e = 0; e < CC; e++) acc = fmaf(xp[e], fp[e * 64], acc);
                float f_a = acc + fa[v * FA_S + c];
                float f = (f_a * gate + fcA[c * VV + v]) * 0.5f;
                float o = fmaf(f, sc2[c], sh2[c]);
                os[(long)c * TT * VV + v] = fmaxf(o, 0.f);
            }
        }
        // next-iteration top __syncthreads() protects fa/xo/fcA reuse
    }
}

extern "C" void kernel_launch(void* const* d_in, const int* in_sizes, int n_in,
                              void* d_out, int out_size)
{
    (void)in_sizes; (void)n_in; (void)out_size;
    const float* x      = (const float*)d_in[0];
    const float* A      = (const float*)d_in[1];
    const float* bn1g   = (const float*)d_in[2];
    const float* bn1b   = (const float*)d_in[3];
    const float* bn1m   = (const float*)d_in[4];
    const float* bn1v   = (const float*)d_in[5];
    const float* conv_w = (const float*)d_in[6];
    const float* conv_b = (const float*)d_in[7];
    const float* ln_g   = (const float*)d_in[8];
    const float* ln_b   = (const float*)d_in[9];
    const float* wq     = (const float*)d_in[10];
    const float* wk     = (const float*)d_in[11];
    const float* wv     = (const float*)d_in[12];
    const float* fc_w   = (const float*)d_in[13];
    const float* gate   = (const float*)d_in[14];
    const float* bn2g   = (const float*)d_in[15];
    const float* bn2b   = (const float*)d_in[16];
    const float* bn2m   = (const float*)d_in[17];
    const float* bn2v   = (const float*)d_in[18];

    const int smem_bytes = SMEM_FLOATS * 4;
    cudaFuncSetAttribute(gcn_kernel, cudaFuncAttributeMaxDynamicSharedMemorySize, smem_bytes);

    reset_counter_kernel<<<1, 1>>>();
    gcn_kernel<<<GRID, NTH, smem_bytes>>>(
        x, A, bn1g, bn1b, bn1m, bn1v, conv_w, conv_b, ln_g, ln_b,
        wq, wk, wv, fc_w, gate, bn2g, bn2b, bn2m, bn2v, (float*)d_out);
}

// round 8
// speedup vs baseline: 1.4196x; 1.4196x over previous
#include <cuda_runtime.h>

// IntentGCN fused kernel for GB300 (sm_103a). Round 2 design (7th submit; six
// infra timeouts): register-tiled float4 GEMM, 512 threads/CTA, conflict-free
// strides. Shapes: N=32, C=64, T=300, V=25, K=3, H=4, DK=DV=16. 9600 slices.

#define NTH 512
#define GRID 152
#define NSLICE 9600
#define CC 64
#define VV 25
#define TT 300

__device__ int g_counter;

__global__ void reset_counter_kernel() { g_counter = 0; }

// ---- shared memory layout (float offsets, all 16B-aligned) ----
// sW[c][j], j in [0,384), stride 388:
//   [0,192): conv (operand fa)   sW[c][o]     = conv_w[o*64+c]
//   [192,256): k  (operand fa)   sW[c][192+d] = wk[c*64+d]
//   [256,320): v  (operand fa)   sW[c][256+d] = wv[c*64+d]
//   [320,384): q  (operand qn)   sW[c][320+d] = wq[c*64+d]
constexpr int SW_S = 388;
constexpr int FA_S = 68;
constexpr int GO_S = 388;
constexpr int XO_S = 65;
constexpr int AW   = 28;   // padded A col stride

constexpr int OFF_SW  = 0;                      // 64*388 = 24832
constexpr int OFF_SA  = OFF_SW + 64*SW_S;       // 3*25*28 = 2100
constexpr int OFF_SFC = OFF_SA + 3*VV*AW;       // 4096
constexpr int OFF_SC1 = OFF_SFC + 4096;
constexpr int OFF_SH1 = OFF_SC1 + 64;
constexpr int OFF_SC2 = OFF_SH1 + 64;
constexpr int OFF_SH2 = OFF_SC2 + 64;
constexpr int OFF_LNG = OFF_SH2 + 64;
constexpr int OFF_LNB = OFF_LNG + 64;
constexpr int OFF_CB  = OFF_LNB + 64;           // 192
constexpr int OFF_FA  = OFF_CB + 192;           // 25*68
constexpr int OFF_QN  = OFF_FA + VV*FA_S;       // 25*68
constexpr int OFF_GO  = OFF_QN + VV*FA_S;       // 25*388
constexpr int OFF_ATT = OFF_GO + VV*GO_S;       // 2500
constexpr int OFF_XO  = OFF_ATT + 2500;         // 25*65 = 1625
constexpr int OFF_FCA = ((OFF_XO + VV*XO_S + 3) / 4) * 4;  // 64*28
constexpr int SMEM_FLOATS = OFF_FCA + 64*AW;    // ~50624 floats = 202496 B

__global__ void __launch_bounds__(NTH, 1)
gcn_kernel(const float* __restrict__ x,      const float* __restrict__ A,
           const float* __restrict__ bn1g,   const float* __restrict__ bn1b,
           const float* __restrict__ bn1m,   const float* __restrict__ bn1v,
           const float* __restrict__ conv_w, const float* __restrict__ conv_b,
           const float* __restrict__ ln_g,   const float* __restrict__ ln_b,
           const float* __restrict__ wq,     const float* __restrict__ wk,
           const float* __restrict__ wv,     const float* __restrict__ fc_w,
           const float* __restrict__ gatep,
           const float* __restrict__ bn2g,   const float* __restrict__ bn2b,
           const float* __restrict__ bn2m,   const float* __restrict__ bn2v,
           float* __restrict__ out)
{
    extern __shared__ float sm[];
    float* sW  = sm + OFF_SW;
    float* sA  = sm + OFF_SA;
    float* sfc = sm + OFF_SFC;
    float* sc1 = sm + OFF_SC1; float* sh1 = sm + OFF_SH1;
    float* sc2 = sm + OFF_SC2; float* sh2 = sm + OFF_SH2;
    float* lng = sm + OFF_LNG; float* lnb = sm + OFF_LNB;
    float* scb = sm + OFF_CB;
    float* fa  = sm + OFF_FA;
    float* qn  = sm + OFF_QN;
    float* go  = sm + OFF_GO;
    float* att = sm + OFF_ATT;
    float* xo  = sm + OFF_XO;
    float* fcA = sm + OFF_FCA;

    const int tid = threadIdx.x;
    const float gate = __ldg(gatep);

    // ---- one-time weight staging ----
    for (int i = tid; i < 192*64; i += NTH) {
        int o = i >> 6, c = i & 63;
        sW[c*SW_S + o] = conv_w[i];
    }
    for (int i = tid; i < 4096; i += NTH) {
        int c = i >> 6, d = i & 63;
        sW[c*SW_S + 192 + d] = wk[i];
        sW[c*SW_S + 256 + d] = wv[i];
        sW[c*SW_S + 320 + d] = wq[i];
        sfc[i] = fc_w[i];
    }
    // A with padded col stride 28 (pad zeros)
    for (int i = tid; i < 3*VV*AW; i += NTH) {
        int kv = i / AW, w = i - kv * AW;
        sA[i] = (w < VV) ? A[kv * VV + w] : 0.f;
    }
    if (tid < 192) scb[tid] = conv_b[tid];
    if (tid < 64) {
        float s1 = bn1g[tid] * rsqrtf(bn1v[tid] + 1e-5f);
        sc1[tid] = s1; sh1[tid] = bn1b[tid] - bn1m[tid] * s1;
        float s2 = bn2g[tid] * rsqrtf(bn2v[tid] + 1e-5f);
        sc2[tid] = s2; sh2[tid] = bn2b[tid] - bn2m[tid] * s2;
        lng[tid] = ln_g[tid]; lnb[tid] = ln_b[tid];
    }
    __shared__ int s_slice;
    __syncthreads();

    const int wid = tid >> 5, lane = tid & 31;

    for (;;) {
        if (tid == 0) s_slice = atomicAdd(&g_counter, 1);
        __syncthreads();               // also fences previous slice's readers
        const int slice = s_slice;
        if (slice >= NSLICE) break;
        const int n = slice / TT, t = slice - n * TT;

        // ---- Step A: load x slice, BN1, transpose -> fa[v][c] ----
        {
            const float* xs = x + ((long)n * CC * TT + t) * VV;
            for (int i = tid; i < CC * VV; i += NTH) {
                int c = i / VV, v = i - c * VV;
                float val = xs[(long)c * TT * VV + v];
                fa[v * FA_S + c] = fmaf(val, sc1[c], sh1[c]);
            }
        }
        __syncthreads();

        // ---- Step A2: LayerNorm per joint -> qn[v][c] ----
        for (int v = wid; v < VV; v += 16) {
            float a0 = fa[v * FA_S + lane];
            float a1 = fa[v * FA_S + 32 + lane];
            float s = a0 + a1, sq = a0 * a0 + a1 * a1;
            #pragma unroll
            for (int off = 16; off; off >>= 1) {
                s  += __shfl_xor_sync(0xffffffffu, s, off);
                sq += __shfl_xor_sync(0xffffffffu, sq, off);
            }
            float mu = s * (1.f / 64.f);
            float var = sq * (1.f / 64.f) - mu * mu;
            float rstd = rsqrtf(var + 1e-6f);
            qn[v * FA_S + lane]      = fmaf((a0 - mu) * rstd, lng[lane],      lnb[lane]);
            qn[v * FA_S + 32 + lane] = fmaf((a1 - mu) * rstd, lng[lane + 32], lnb[lane + 32]);
        }
        __syncthreads();

        // ---- Step B: combined GEMM [25 x 64] @ [64 x 384] -> go[v][j] ----
        // 480 active threads: vg=tid/96 owns 5 v-rows, jg=tid%96 owns 4 j-cols.
        if (tid < 480) {
            const int vg = tid / 96;
            const int jg = tid - vg * 96;
            const int j0 = jg * 4;
            const float* opb = ((j0 >= 320) ? qn : fa) + vg * 5 * FA_S;
            float acc[5][4];
            #pragma unroll
            for (int vi = 0; vi < 5; vi++)
                #pragma unroll
                for (int jj = 0; jj < 4; jj++) acc[vi][jj] = 0.f;

            #pragma unroll 4
            for (int c = 0; c < CC; c += 4) {
                float4 f4[5];
                #pragma unroll
                for (int vi = 0; vi < 5; vi++)
                    f4[vi] = *(const float4*)(opb + vi * FA_S + c);
                #pragma unroll
                for (int i = 0; i < 4; i++) {
                    float4 w4 = *(const float4*)(sW + (c + i) * SW_S + j0);
                    #pragma unroll
                    for (int vi = 0; vi < 5; vi++) {
                        float f = (i == 0) ? f4[vi].x : (i == 1) ? f4[vi].y
                                : (i == 2) ? f4[vi].z : f4[vi].w;
                        acc[vi][0] = fmaf(f, w4.x, acc[vi][0]);
                        acc[vi][1] = fmaf(f, w4.y, acc[vi][1]);
                        acc[vi][2] = fmaf(f, w4.z, acc[vi][2]);
                        acc[vi][3] = fmaf(f, w4.w, acc[vi][3]);
                    }
                }
            }
            float4 b4 = make_float4(0.f, 0.f, 0.f, 0.f);
            if (j0 < 192) b4 = *(const float4*)(scb + j0);
            #pragma unroll
            for (int vi = 0; vi < 5; vi++) {
                float4 r;
                r.x = acc[vi][0] + b4.x; r.y = acc[vi][1] + b4.y;
                r.z = acc[vi][2] + b4.z; r.w = acc[vi][3] + b4.w;
                *(float4*)(go + (vg * 5 + vi) * GO_S + j0) = r;
            }
        }
        __syncthreads();

        // ---- Step C: fixed-branch A contraction (448 threads) ----
        // fcA[c][w0..w0+3] = sum_{k,v} go[v][k*64+c] * A[k][v][w]
        if (tid < 448) {
            const int c = tid / 7, wg = tid - (tid / 7) * 7, w0 = wg * 4;
            float4 acc = make_float4(0.f, 0.f, 0.f, 0.f);
            #pragma unroll
            for (int k = 0; k < 3; k++) {
                const float* gp = go + k * 64 + c;
                const float* ap = sA + k * VV * AW + w0;
                #pragma unroll
                for (int v = 0; v < VV; v++) {
                    float g = gp[v * GO_S];
                    float4 a4 = *(const float4*)(ap + v * AW);
                    acc.x = fmaf(g, a4.x, acc.x);
                    acc.y = fmaf(g, a4.y, acc.y);
                    acc.z = fmaf(g, a4.z, acc.z);
                    acc.w = fmaf(g, a4.w, acc.w);
                }
            }
            *(float4*)(fcA + c * AW + w0) = acc;
        }
        // ---- Step D1: attention scores (same phase; read-only on go) ----
        for (int i = tid; i < 4 * VV * VV; i += NTH) {
            int h = i / 625, r = i - h * 625;
            int qi = r / VV, kj = r - qi * VV;
            const float4* qp = (const float4*)(go + qi * GO_S + 320 + h * 16);
            const float4* kp = (const float4*)(go + kj * GO_S + 192 + h * 16);
            float acc = 0.f;
            #pragma unroll
            for (int d = 0; d < 4; d++) {
                float4 q4 = qp[d], k4 = kp[d];
                acc = fmaf(q4.x, k4.x, acc);
                acc = fmaf(q4.y, k4.y, acc);
                acc = fmaf(q4.z, k4.z, acc);
                acc = fmaf(q4.w, k4.w, acc);
            }
            att[(h * VV + qi) * VV + kj] = acc * 0.25f;
        }
        __syncthreads();

        // ---- Step D2: softmax over last dim (100 rows of 25) ----
        if (tid < 100) {
            float* row = att + tid * VV;
            float m = row[0];
            #pragma unroll
            for (int j = 1; j < VV; j++) m = fmaxf(m, row[j]);
            float e[VV]; float s = 0.f;
            #pragma unroll
            for (int j = 0; j < VV; j++) { e[j] = __expf(row[j] - m); s += e[j]; }
            float inv = 1.f / s;
            #pragma unroll
            for (int j = 0; j < VV; j++) row[j] = e[j] * inv;
        }
        __syncthreads();

        // ---- Step D3: xo[v][e] = sum_j attn[h,v,j] * vv[j][e] ----
        for (int i = tid; i < VV * CC; i += NTH) {
            int v = i >> 6, e = i & 63, h = e >> 4;
            const float* ap = att + (h * VV + v) * VV;
            const float* vp = go + 256 + e;
            float acc = 0.f;
            #pragma unroll
            for (int j = 0; j < VV; j++) acc = fmaf(ap[j], vp[j * GO_S], acc);
            xo[v * XO_S + e] = acc;
        }
        __syncthreads();

        // ---- Step E: fc + residual, gate mix, BN2, ReLU, store ----
        {
            float* os = out + ((long)n * CC * TT + t) * VV;
            for (int i = tid; i < CC * VV; i += NTH) {
                int c = i / VV, v = i - c * VV;
                const float* xp = xo + v * XO_S;
                const float* fp = sfc + c;
                float acc = 0.f;
                #pragma unroll
                for (int e = 0; e < CC; e++) acc = fmaf(xp[e], fp[e * 64], acc);
                float f_a = acc + fa[v * FA_S + c];
                float f = (f_a * gate + fcA[c * AW + v]) * 0.5f;
                float o = fmaf(f, sc2[c], sh2[c]);
                os[(long)c * TT * VV + v] = fmaxf(o, 0.f);
            }
        }
        // next-iteration top __syncthreads() protects fa/xo/fcA reuse
    }
}

extern "C" void kernel_launch(void* const* d_in, const int* in_sizes, int n_in,
                              void* d_out, int out_size)
{
    (void)in_sizes; (void)n_in; (void)out_size;
    const float* x      = (const float*)d_in[0];
    const float* A      = (const float*)d_in[1];
    const float* bn1g   = (const float*)d_in[2];
    const float* bn1b   = (const float*)d_in[3];
    const float* bn1m   = (const float*)d_in[4];
    const float* bn1v   = (const float*)d_in[5];
    const float* conv_w = (const float*)d_in[6];
    const float* conv_b = (const float*)d_in[7];
    const float* ln_g   = (const float*)d_in[8];
    const float* ln_b   = (const float*)d_in[9];
    const float* wq     = (const float*)d_in[10];
    const float* wk     = (const float*)d_in[11];
    const float* wv     = (const float*)d_in[12];
    const float* fc_w   = (const float*)d_in[13];
    const float* gate   = (const float*)d_in[14];
    const float* bn2g   = (const float*)d_in[15];
    const float* bn2b   = (const float*)d_in[16];
    const float* bn2m   = (const float*)d_in[17];
    const float* bn2v   = (const float*)d_in[18];

    const int smem_bytes = SMEM_FLOATS * 4;
    cudaFuncSetAttribute(gcn_kernel, cudaFuncAttributeMaxDynamicSharedMemorySize, smem_bytes);

    reset_counter_kernel<<<1, 1>>>();
    gcn_kernel<<<GRID, NTH, smem_bytes>>>(
        x, A, bn1g, bn1b, bn1m, bn1v, conv_w, conv_b, ln_g, ln_b,
        wq, wk, wv, fc_w, gate, bn2g, bn2b, bn2m, bn2v, (float*)d_out);
}

// round 11
// speedup vs baseline: 1.6891x; 1.1898x over previous
#include <cuda_runtime.h>

// IntentGCN fused kernel, GB300 (sm_103a). R9 design (3rd submit; infra
// timeouts): broadcast-structured E/D3/D1 (lane=v, warp=col-tile), transposed
// xoT/sfcT; B unchanged from verified R8.
// Shapes: N=32, C=64, T=300, V=25, K=3, H=4, DK=DV=16. 9600 slices.

#define NTH 512
#define GRID 152
#define NSLICE 9600
#define CC 64
#define VV 25
#define TT 300

__device__ int g_counter;

__global__ void reset_counter_kernel() { g_counter = 0; }

constexpr int SW_S = 388;
constexpr int FA_S = 68;
constexpr int GO_S = 388;
constexpr int AW   = 28;   // padded stride for A / fcA / xoT rows
constexpr int FCT_S = 68;  // sfcT row stride

constexpr int OFF_SW  = 0;                       // 64*388 = 24832
constexpr int OFF_SA  = OFF_SW + 64*SW_S;        // 2100
constexpr int OFF_SFC = OFF_SA + 3*VV*AW;        // sfcT: 64*68 = 4352
constexpr int OFF_SC1 = OFF_SFC + 64*FCT_S;
constexpr int OFF_SH1 = OFF_SC1 + 64;
constexpr int OFF_SC2 = OFF_SH1 + 64;
constexpr int OFF_SH2 = OFF_SC2 + 64;
constexpr int OFF_LNG = OFF_SH2 + 64;
constexpr int OFF_LNB = OFF_LNG + 64;
constexpr int OFF_CB  = OFF_LNB + 64;            // 192
constexpr int OFF_FA  = OFF_CB + 192;            // 25*68
constexpr int OFF_QN  = OFF_FA + VV*FA_S;        // 25*68
constexpr int OFF_GO  = OFF_QN + VV*FA_S;        // 25*388
constexpr int OFF_ATT = OFF_GO + VV*GO_S;        // 2500
constexpr int OFF_XOT = OFF_ATT + 2500;          // xoT[e][v]: 64*28 = 1792
constexpr int OFF_FCA = OFF_XOT + 64*AW;         // fcA[c][v]: 64*28 = 1792
constexpr int SMEM_FLOATS = OFF_FCA + 64*AW;     // 51044 floats = 204176 B

__global__ void __launch_bounds__(NTH, 1)
gcn_kernel(const float* __restrict__ x,      const float* __restrict__ A,
           const float* __restrict__ bn1g,   const float* __restrict__ bn1b,
           const float* __restrict__ bn1m,   const float* __restrict__ bn1v,
           const float* __restrict__ conv_w, const float* __restrict__ conv_b,
           const float* __restrict__ ln_g,   const float* __restrict__ ln_b,
           const float* __restrict__ wq,     const float* __restrict__ wk,
           const float* __restrict__ wv,     const float* __restrict__ fc_w,
           const float* __restrict__ gatep,
           const float* __restrict__ bn2g,   const float* __restrict__ bn2b,
           const float* __restrict__ bn2m,   const float* __restrict__ bn2v,
           float* __restrict__ out)
{
    extern __shared__ float sm[];
    float* sW   = sm + OFF_SW;
    float* sA   = sm + OFF_SA;
    float* sfcT = sm + OFF_SFC;
    float* sc1 = sm + OFF_SC1; float* sh1 = sm + OFF_SH1;
    float* sc2 = sm + OFF_SC2; float* sh2 = sm + OFF_SH2;
    float* lng = sm + OFF_LNG; float* lnb = sm + OFF_LNB;
    float* scb = sm + OFF_CB;
    float* fa  = sm + OFF_FA;
    float* qn  = sm + OFF_QN;
    float* go  = sm + OFF_GO;
    float* att = sm + OFF_ATT;
    float* xoT = sm + OFF_XOT;
    float* fcA = sm + OFF_FCA;

    const int tid = threadIdx.x;
    const float gate = __ldg(gatep);

    // ---- one-time weight staging ----
    for (int i = tid; i < 192*64; i += NTH) {
        int o = i >> 6, c = i & 63;
        sW[c*SW_S + o] = conv_w[i];
    }
    for (int i = tid; i < 4096; i += NTH) {
        int c = i >> 6, d = i & 63;
        sW[c*SW_S + 192 + d] = wk[i];
        sW[c*SW_S + 256 + d] = wv[i];
        sW[c*SW_S + 320 + d] = wq[i];
        sfcT[c*FCT_S + d] = fc_w[i];    // sfcT[e][c] = fc_w[e*64+c]
    }
    for (int i = tid; i < 3*VV*AW; i += NTH) {
        int kv = i / AW, w = i - kv * AW;
        sA[i] = (w < VV) ? A[kv * VV + w] : 0.f;
    }
    if (tid < 192) scb[tid] = conv_b[tid];
    if (tid < 64) {
        float s1 = bn1g[tid] * rsqrtf(bn1v[tid] + 1e-5f);
        sc1[tid] = s1; sh1[tid] = bn1b[tid] - bn1m[tid] * s1;
        float s2 = bn2g[tid] * rsqrtf(bn2v[tid] + 1e-5f);
        sc2[tid] = s2; sh2[tid] = bn2b[tid] - bn2m[tid] * s2;
        lng[tid] = ln_g[tid]; lnb[tid] = ln_b[tid];
    }
    __shared__ int s_slice;
    __syncthreads();

    const int wid = tid >> 5, lane = tid & 31;

    for (;;) {
        if (tid == 0) s_slice = atomicAdd(&g_counter, 1);
        __syncthreads();               // also fences previous slice's readers
        const int slice = s_slice;
        if (slice >= NSLICE) break;
        const int n = slice / TT, t = slice - n * TT;

        // ---- Step A: load x slice, BN1, transpose -> fa[v][c] ----
        {
            const float* xs = x + ((long)n * CC * TT + t) * VV;
            for (int i = tid; i < CC * VV; i += NTH) {
                int c = i / VV, v = i - c * VV;
                float val = xs[(long)c * TT * VV + v];
                fa[v * FA_S + c] = fmaf(val, sc1[c], sh1[c]);
            }
        }
        __syncthreads();

        // ---- Step A2: LayerNorm per joint -> qn[v][c] ----
        for (int v = wid; v < VV; v += 16) {
            float a0 = fa[v * FA_S + lane];
            float a1 = fa[v * FA_S + 32 + lane];
            float s = a0 + a1, sq = a0 * a0 + a1 * a1;
            #pragma unroll
            for (int off = 16; off; off >>= 1) {
                s  += __shfl_xor_sync(0xffffffffu, s, off);
                sq += __shfl_xor_sync(0xffffffffu, sq, off);
            }
            float mu = s * (1.f / 64.f);
            float var = sq * (1.f / 64.f) - mu * mu;
            float rstd = rsqrtf(var + 1e-6f);
            qn[v * FA_S + lane]      = fmaf((a0 - mu) * rstd, lng[lane],      lnb[lane]);
            qn[v * FA_S + 32 + lane] = fmaf((a1 - mu) * rstd, lng[lane + 32], lnb[lane + 32]);
        }
        __syncthreads();

        // ---- Step B: combined GEMM [25 x 64] @ [64 x 384] -> go[v][j] ----
        if (tid < 480) {
            const int vg = tid / 96;
            const int jg = tid - vg * 96;
            const int j0 = jg * 4;
            const float* opb = ((j0 >= 320) ? qn : fa) + vg * 5 * FA_S;
            float acc[5][4];
            #pragma unroll
            for (int vi = 0; vi < 5; vi++)
                #pragma unroll
                for (int jj = 0; jj < 4; jj++) acc[vi][jj] = 0.f;

            #pragma unroll 4
            for (int c = 0; c < CC; c += 4) {
                float4 f4[5];
                #pragma unroll
                for (int vi = 0; vi < 5; vi++)
                    f4[vi] = *(const float4*)(opb + vi * FA_S + c);
                #pragma unroll
                for (int i = 0; i < 4; i++) {
                    float4 w4 = *(const float4*)(sW + (c + i) * SW_S + j0);
                    #pragma unroll
                    for (int vi = 0; vi < 5; vi++) {
                        float f = (i == 0) ? f4[vi].x : (i == 1) ? f4[vi].y
                                : (i == 2) ? f4[vi].z : f4[vi].w;
                        acc[vi][0] = fmaf(f, w4.x, acc[vi][0]);
                        acc[vi][1] = fmaf(f, w4.y, acc[vi][1]);
                        acc[vi][2] = fmaf(f, w4.z, acc[vi][2]);
                        acc[vi][3] = fmaf(f, w4.w, acc[vi][3]);
                    }
                }
            }
            float4 b4 = make_float4(0.f, 0.f, 0.f, 0.f);
            if (j0 < 192) b4 = *(const float4*)(scb + j0);
            #pragma unroll
            for (int vi = 0; vi < 5; vi++) {
                float4 r;
                r.x = acc[vi][0] + b4.x; r.y = acc[vi][1] + b4.y;
                r.z = acc[vi][2] + b4.z; r.w = acc[vi][3] + b4.w;
                *(float4*)(go + (vg * 5 + vi) * GO_S + j0) = r;
            }
        }
        __syncthreads();

        // ---- Step C: fixed-branch A contraction (448 threads) ----
        if (tid < 448) {
            const int c = tid / 7, wg = tid - (tid / 7) * 7, w0 = wg * 4;
            float4 acc = make_float4(0.f, 0.f, 0.f, 0.f);
            #pragma unroll
            for (int k = 0; k < 3; k++) {
                const float* gp = go + k * 64 + c;
                const float* ap = sA + k * VV * AW + w0;
                #pragma unroll
                for (int v = 0; v < VV; v++) {
                    float g = gp[v * GO_S];
                    float4 a4 = *(const float4*)(ap + v * AW);
                    acc.x = fmaf(g, a4.x, acc.x);
                    acc.y = fmaf(g, a4.y, acc.y);
                    acc.z = fmaf(g, a4.z, acc.z);
                    acc.w = fmaf(g, a4.w, acc.w);
                }
            }
            *(float4*)(fcA + c * AW + w0) = acc;
        }
        // ---- Step D1: attention scores; K-fragments held in registers ----
        // warp w: head h = w>>2, qi in {w&3, w&3+4, ...}; lane = kj.
        {
            const int h = wid >> 2, r = wid & 3;
            float4 k0 = make_float4(0.f,0.f,0.f,0.f), k1 = k0, k2 = k0, k3 = k0;
            if (lane < VV) {
                const float* kp = go + lane * GO_S + 192 + h * 16;
                k0 = *(const float4*)(kp);
                k1 = *(const float4*)(kp + 4);
                k2 = *(const float4*)(kp + 8);
                k3 = *(const float4*)(kp + 12);
            }
            for (int qi = r; qi < VV; qi += 4) {
                const float* qp = go + qi * GO_S + 320 + h * 16;
                float4 q0 = *(const float4*)(qp);
                float4 q1 = *(const float4*)(qp + 4);
                float4 q2 = *(const float4*)(qp + 8);
                float4 q3 = *(const float4*)(qp + 12);
                if (lane < VV) {
                    float acc = q0.x*k0.x + q0.y*k0.y + q0.z*k0.z + q0.w*k0.w;
                    acc = fmaf(q1.x, k1.x, acc); acc = fmaf(q1.y, k1.y, acc);
                    acc = fmaf(q1.z, k1.z, acc); acc = fmaf(q1.w, k1.w, acc);
                    acc = fmaf(q2.x, k2.x, acc); acc = fmaf(q2.y, k2.y, acc);
                    acc = fmaf(q2.z, k2.z, acc); acc = fmaf(q2.w, k2.w, acc);
                    acc = fmaf(q3.x, k3.x, acc); acc = fmaf(q3.y, k3.y, acc);
                    acc = fmaf(q3.z, k3.z, acc); acc = fmaf(q3.w, k3.w, acc);
                    att[(h * VV + qi) * VV + lane] = acc * 0.25f;
                }
            }
        }
        __syncthreads();

        // ---- Step D2: softmax over last dim (100 rows of 25) ----
        if (tid < 100) {
            float* row = att + tid * VV;
            float m = row[0];
            #pragma unroll
            for (int j = 1; j < VV; j++) m = fmaxf(m, row[j]);
            float e[VV]; float s = 0.f;
            #pragma unroll
            for (int j = 0; j < VV; j++) { e[j] = __expf(row[j] - m); s += e[j]; }
            float inv = 1.f / s;
            #pragma unroll
            for (int j = 0; j < VV; j++) row[j] = e[j] * inv;
        }
        __syncthreads();

        // ---- Step D3: xoT[e][v] = sum_j attn[h,v,j] * vv[j][e] ----
        // warp w: e-cols e0 = w*4 (head h = e0>>4); lane = v.
        {
            const int e0 = wid * 4, h = e0 >> 4;
            if (lane < VV) {
                const float* ap = att + (h * VV + lane) * VV;
                const float* gp = go + 256 + e0;
                float4 acc = make_float4(0.f, 0.f, 0.f, 0.f);
                #pragma unroll
                for (int j = 0; j < VV; j++) {
                    float a = ap[j];
                    float4 v4 = *(const float4*)(gp + j * GO_S);   // broadcast
                    acc.x = fmaf(a, v4.x, acc.x);
                    acc.y = fmaf(a, v4.y, acc.y);
                    acc.z = fmaf(a, v4.z, acc.z);
                    acc.w = fmaf(a, v4.w, acc.w);
                }
                xoT[(e0 + 0) * AW + lane] = acc.x;
                xoT[(e0 + 1) * AW + lane] = acc.y;
                xoT[(e0 + 2) * AW + lane] = acc.z;
                xoT[(e0 + 3) * AW + lane] = acc.w;
            }
        }
        __syncthreads();

        // ---- Step E: out = relu(bn2((xo@fc + fa)*gate + fcA)*0.5) ----
        // warp w: c-cols c0 = w*4; lane = v. fc weights broadcast.
        {
            const int c0 = wid * 4;
            if (lane < VV) {
                const int v = lane;
                float4 acc = make_float4(0.f, 0.f, 0.f, 0.f);
                const float* xp = xoT + v;
                const float* wp = sfcT + c0;
                #pragma unroll 16
                for (int e = 0; e < CC; e++) {
                    float xval = xp[e * AW];
                    float4 w4 = *(const float4*)(wp + e * FCT_S);  // broadcast
                    acc.x = fmaf(xval, w4.x, acc.x);
                    acc.y = fmaf(xval, w4.y, acc.y);
                    acc.z = fmaf(xval, w4.z, acc.z);
                    acc.w = fmaf(xval, w4.w, acc.w);
                }
                float4 res = *(const float4*)(fa + v * FA_S + c0);
                float* os = out + ((long)n * CC * TT + t) * VV;
                #pragma unroll
                for (int i = 0; i < 4; i++) {
                    float fa_ = (i == 0) ? acc.x + res.x : (i == 1) ? acc.y + res.y
                              : (i == 2) ? acc.z + res.z : acc.w + res.w;
                    float f = (fa_ * gate + fcA[(c0 + i) * AW + v]) * 0.5f;
                    float o = fmaf(f, sc2[c0 + i], sh2[c0 + i]);
                    os[(long)(c0 + i) * TT * VV + v] = fmaxf(o, 0.f);
                }
            }
        }
        // next-iteration top __syncthreads() protects fa/xoT/fcA reuse
    }
}

extern "C" void kernel_launch(void* const* d_in, const int* in_sizes, int n_in,
                              void* d_out, int out_size)
{
    (void)in_sizes; (void)n_in; (void)out_size;
    const float* x      = (const float*)d_in[0];
    const float* A      = (const float*)d_in[1];
    const float* bn1g   = (const float*)d_in[2];
    const float* bn1b   = (const float*)d_in[3];
    const float* bn1m   = (const float*)d_in[4];
    const float* bn1v   = (const float*)d_in[5];
    const float* conv_w = (const float*)d_in[6];
    const float* conv_b = (const float*)d_in[7];
    const float* ln_g   = (const float*)d_in[8];
    const float* ln_b   = (const float*)d_in[9];
    const float* wq     = (const float*)d_in[10];
    const float* wk     = (const float*)d_in[11];
    const float* wv     = (const float*)d_in[12];
    const float* fc_w   = (const float*)d_in[13];
    const float* gate   = (const float*)d_in[14];
    const float* bn2g   = (const float*)d_in[15];
    const float* bn2b   = (const float*)d_in[16];
    const float* bn2m   = (const float*)d_in[17];
    const float* bn2v   = (const float*)d_in[18];

    const int smem_bytes = SMEM_FLOATS * 4;
    cudaFuncSetAttribute(gcn_kernel, cudaFuncAttributeMaxDynamicSharedMemorySize, smem_bytes);

    reset_counter_kernel<<<1, 1>>>();
    gcn_kernel<<<GRID, NTH, smem_bytes>>>(
        x, A, bn1g, bn1b, bn1m, bn1v, conv_w, conv_b, ln_g, ln_b,
        wq, wk, wv, fc_w, gate, bn2g, bn2b, bn2m, bn2v, (float*)d_out);
}